// round 15
// baseline (speedup 1.0000x reference)
#include <cuda_runtime.h>
#include <cuda_bf16.h>
#include <cuda_fp16.h>
#include <cstdint>

#define B_SZ   64
#define SEQ    197
#define C_DIM  768
#define H_NUM  12
#define HDIM   64
#define M_ROWS (B_SZ * SEQ)          // 12608

// ---------------------------------------------------------------------------
// Scratch (allocation-free: __device__ globals), all single fp16
// ---------------------------------------------------------------------------
__device__ __half g_xh [M_ROWS * C_DIM];            // x
__device__ __half g_wqh[3 * C_DIM * C_DIM];         // w_qkv
__device__ __half g_wph[C_DIM * C_DIM];             // w_proj
__device__ __half g_qf [B_SZ * H_NUM * SEQ * HDIM]; // q/k/v
__device__ __half g_kf [B_SZ * H_NUM * SEQ * HDIM];
__device__ __half g_vf [B_SZ * H_NUM * SEQ * HDIM];
__device__ __half g_aoh[M_ROWS * C_DIM];            // attn out

// ---------------------------------------------------------------------------
// Base-feature PTX helpers
// ---------------------------------------------------------------------------
__device__ __forceinline__ uint32_t smem_u32(const void* p) {
    uint32_t a;
    asm("{ .reg .u64 t; cvta.to.shared.u64 t, %1; cvt.u32.u64 %0, t; }"
        : "=r"(a) : "l"(p));
    return a;
}

__device__ __forceinline__ void cp_async16(uint32_t dst, const void* src, bool pred) {
    const int sz = pred ? 16 : 0;
    asm volatile("cp.async.cg.shared.global [%0], [%1], 16, %2;"
                 :: "r"(dst), "l"(src), "r"(sz) : "memory");
}
#define CP_COMMIT()  asm volatile("cp.async.commit_group;" ::: "memory")
#define CP_WAIT1()   asm volatile("cp.async.wait_group 1;" ::: "memory")
#define CP_WAIT0()   asm volatile("cp.async.wait_group 0;" ::: "memory")

__device__ __forceinline__ void ldm_x4(uint32_t* r, uint32_t addr) {
    asm volatile("ldmatrix.sync.aligned.m8n8.x4.shared.b16 {%0,%1,%2,%3}, [%4];"
                 : "=r"(r[0]), "=r"(r[1]), "=r"(r[2]), "=r"(r[3]) : "r"(addr));
}
__device__ __forceinline__ void ldm_x2(uint32_t* r, uint32_t addr) {
    asm volatile("ldmatrix.sync.aligned.m8n8.x2.shared.b16 {%0,%1}, [%2];"
                 : "=r"(r[0]), "=r"(r[1]) : "r"(addr));
}
__device__ __forceinline__ void ldm_x4_t(uint32_t* r, uint32_t addr) {
    asm volatile("ldmatrix.sync.aligned.m8n8.x4.trans.shared.b16 {%0,%1,%2,%3}, [%4];"
                 : "=r"(r[0]), "=r"(r[1]), "=r"(r[2]), "=r"(r[3]) : "r"(addr));
}
__device__ __forceinline__ void mma_f16(float* c, const uint32_t* a, const uint32_t* b) {
    asm volatile(
        "mma.sync.aligned.m16n8k16.row.col.f32.f16.f16.f32 "
        "{%0,%1,%2,%3}, {%4,%5,%6,%7}, {%8,%9}, {%0,%1,%2,%3};"
        : "+f"(c[0]), "+f"(c[1]), "+f"(c[2]), "+f"(c[3])
        : "r"(a[0]), "r"(a[1]), "r"(a[2]), "r"(a[3]), "r"(b[0]), "r"(b[1]));
}

// ---------------------------------------------------------------------------
// Fused fp32 -> fp16 cast: one launch covers x, w_qkv, w_proj.
// ---------------------------------------------------------------------------
#define N4X (M_ROWS * C_DIM / 4)
#define N4Q (3 * C_DIM * C_DIM / 4)
#define N4P (C_DIM * C_DIM / 4)
#define N4ALL (N4X + N4Q + N4P)

__global__ __launch_bounds__(256)
void cast_all(const float* __restrict__ x, const float* __restrict__ wq,
              const float* __restrict__ wp)
{
    const int i = blockIdx.x * 256 + threadIdx.x;
    if (i >= N4ALL) return;
    const float* src;
    __half2* dst;
    int k;
    if (i < N4X)            { src = x;  dst = (__half2*)g_xh;  k = i; }
    else if (i < N4X + N4Q) { src = wq; dst = (__half2*)g_wqh; k = i - N4X; }
    else                    { src = wp; dst = (__half2*)g_wph; k = i - N4X - N4Q; }
    float4 v = ((const float4*)src)[k];
    dst[k * 2 + 0] = __halves2half2(__float2half(v.x), __float2half(v.y));
    dst[k * 2 + 1] = __halves2half2(__float2half(v.z), __float2half(v.w));
}

// ---------------------------------------------------------------------------
// Persistent HMMA fp16 GEMM: C = A * B^T, K=768, fp32 accumulation.
// 128x128 tiles, 296 persistent CTAs (2/SM), 256 threads (8 warps = 2m x 4n),
// BK=64, continuous 3-stage cp.async ring spanning tile boundaries —
// prologue paid once per CTA, epilogue hidden behind next tile's loads.
// MODE 0: A = g_xh, B = g_wqh -> fp16 q/k/v    (18 x 99 tiles)
// MODE 1: A = g_aoh, B = g_wph -> out + bias   ( 6 x 99 tiles)
// ---------------------------------------------------------------------------
#define ROW_B   144
#define A_MAT   (128 * ROW_B)
#define B_MAT   (128 * ROW_B)
#define A_O     0
#define BH_O    A_MAT
#define STG_B   (A_MAT + B_MAT)           // 36864
#define GEMM_SMEM (3 * STG_B)             // 110592
#define NIT     (C_DIM / 64)              // 12
#define G_CTAS  296

template <int MODE>
__global__ __launch_bounds__(256, 2)
void hmma_gemm(const float* __restrict__ bias, float* __restrict__ out)
{
    constexpr int NCOLT = (MODE == 0) ? 18 : 6;
    constexpr int NTIL  = NCOLT * 99;

    extern __shared__ char smem[];
    const uint32_t sb = smem_u32(smem);
    const int tid  = threadIdx.x;
    const int wid  = tid >> 5, lane = tid & 31;
    const int wm   = wid & 1;
    const int wn   = wid >> 1;
    const int bid  = blockIdx.x;
    const int G    = gridDim.x;

    const __half* A = (MODE == 0) ? g_xh : g_aoh;
    const __half* B = (MODE == 0) ? g_wqh : g_wph;

    const int nt  = (NTIL - bid + G - 1) / G;   // tiles for this CTA
    const int tot = nt * NIT;

    // issue K-iter (g % NIT) of tile (bid + (g/NIT)*G) into ring buf (g % 3)
    auto issue = [&](int g) {
        const int t    = bid + (g / NIT) * G;
        const int row0 = (t / NCOLT) * 128;
        const int col0 = (t % NCOLT) * 128;
        const int k0   = (g % NIT) * 64;
        const uint32_t base = sb + (uint32_t)(g % 3) * STG_B;
#pragma unroll
        for (int j = 0; j < 8; j++) {
            const int c = tid + j * 256;
            if (c < 1024) {
                const int r = c >> 3, q = c & 7;
                const int gr = row0 + r;
                const bool av = (gr < M_ROWS);
                const size_t off = (size_t)gr * C_DIM + k0 + q * 8;
                cp_async16(base + A_O + r * ROW_B + q * 16, A + off, av);
            } else {
                const int u = c - 1024;
                const int r = u >> 3, q = u & 7;
                const size_t off = (size_t)(col0 + r) * C_DIM + k0 + q * 8;
                cp_async16(base + BH_O + r * ROW_B + q * 16, B + off, true);
            }
        }
    };

    // A x4 mapping: rows on bit3, 16B col-half on bit4
    const uint32_t aRowSel = (lane & 7) + ((lane >> 3) & 1) * 8;
    const uint32_t aColSel = ((lane >> 4) & 1) * 16;
    // B pairwise x4 mapping: rows on bit4, 16B col-half on bit3
    const uint32_t bRow4 = (lane & 7) + ((lane >> 4) & 1) * 8;
    const uint32_t bCol4 = ((lane >> 3) & 1) * 16;

    float acc[4][4][4];

    issue(0);
    CP_COMMIT();
    issue(1);
    CP_COMMIT();

    for (int gi = 0; gi < tot; gi++) {
        CP_WAIT1();
        __syncthreads();

        const int kit = gi % NIT;
        if (kit == 0) {
#pragma unroll
            for (int mi = 0; mi < 4; mi++)
#pragma unroll
                for (int ni = 0; ni < 4; ni++)
#pragma unroll
                    for (int t = 0; t < 4; t++) acc[mi][ni][t] = 0.f;
        }

        const uint32_t base = sb + (uint32_t)(gi % 3) * STG_B;
#pragma unroll
        for (int ks = 0; ks < 4; ks++) {
            const uint32_t kb = ks * 32;
            uint32_t a_f[4][4];
#pragma unroll
            for (int mi = 0; mi < 4; mi++) {
                const uint32_t ra = base + A_O + (wm * 64 + mi * 16 + aRowSel) * ROW_B + aColSel + kb;
                ldm_x4(a_f[mi], ra);
            }
#pragma unroll
            for (int p = 0; p < 2; p++) {
                uint32_t b4[4];
                const uint32_t rb = base + BH_O + (wn * 32 + p * 16 + bRow4) * ROW_B + bCol4 + kb;
                ldm_x4(b4, rb);
#pragma unroll
                for (int mi = 0; mi < 4; mi++) {
                    mma_f16(acc[mi][2 * p + 0], a_f[mi], b4 + 0);
                    mma_f16(acc[mi][2 * p + 1], a_f[mi], b4 + 2);
                }
            }
        }

        if (gi + 2 < tot) issue(gi + 2);
        CP_COMMIT();

        // ---- epilogue for finished tile (overlaps next tile's loads) ----
        if (kit == NIT - 1) {
            const int t    = bid + (gi / NIT) * G;
            const int row0 = (t / NCOLT) * 128;
            const int col0 = (t % NCOLT) * 128;
#pragma unroll
            for (int mi = 0; mi < 4; mi++) {
                const int rbase = row0 + wm * 64 + mi * 16 + (lane >> 2);
#pragma unroll
                for (int half = 0; half < 2; half++) {
                    const int row = rbase + half * 8;
                    if (row >= M_ROWS) continue;
                    int bb = 0, n = 0;
                    if (MODE == 0) { bb = row / SEQ; n = row - bb * SEQ; }
#pragma unroll
                    for (int ni = 0; ni < 4; ni++) {
                        const int col = col0 + wn * 32 + ni * 8 + 2 * (lane & 3);
                        const float v0 = acc[mi][ni][half * 2 + 0];
                        const float v1 = acc[mi][ni][half * 2 + 1];
                        if (MODE == 0) {
                            const int which = col / C_DIM;
                            const int rem   = col - which * C_DIM;
                            const int h     = rem >> 6;
                            const int d     = rem & 63;
                            __half* dst = (which == 0) ? g_qf : (which == 1 ? g_kf : g_vf);
                            const size_t off = (((size_t)(bb * H_NUM + h)) * SEQ + n) * HDIM + d;
                            *(__half2*)&dst[off] =
                                __halves2half2(__float2half(v0), __float2half(v1));
                        } else {
                            *(float2*)&out[(size_t)row * C_DIM + col] =
                                make_float2(v0 + __ldg(&bias[col]), v1 + __ldg(&bias[col + 1]));
                        }
                    }
                }
            }
        }
    }
}

// ---------------------------------------------------------------------------
// fp16 HMMA attention (unchanged): one CTA per (b,h), 8 warps.
// No max-subtraction, fused bias+exp pass, Q double-buffered.
// ---------------------------------------------------------------------------
#define NP     208
#define KSTR   144
#define PSTR   432
#define KF_OFF 0
#define VF_OFF 29952
#define QF_OFF 59904
#define QBUF_B 9216
#define PF_OFF 78336
#define TB_OFF 105984
#define RC_OFF 109056
#define RS_OFF 110080
#define ATT_SMEM 110592

__global__ __launch_bounds__(256, 2)
void attn_hmma(const float* __restrict__ table)
{
    extern __shared__ char smc[];
    const uint32_t sb = smem_u32(smc);
    float* sT   = (float*)(smc + TB_OFF);
    int*   rcA  = (int*)(smc + RC_OFF);
    float* redS = (float*)(smc + RS_OFF);

    const int tid = threadIdx.x, wid = tid >> 5, lane = tid & 31;
    const int bh = blockIdx.x;
    const int b  = bh / H_NUM;
    const int h  = bh - b * H_NUM;
    const size_t base = (size_t)bh * SEQ * HDIM;

    for (int c = tid; c < NP * 8; c += 256) {
        const int m = c >> 3, q = c & 7;
        const bool v = (m < SEQ);
        const size_t go = base + (size_t)m * HDIM + q * 8;
        const uint32_t so = m * KSTR + q * 16;
        cp_async16(sb + KF_OFF + so, g_kf + (v ? go : base), v);
        cp_async16(sb + VF_OFF + so, g_vf + (v ? go : base), v);
    }
    for (int c = tid; c < 512; c += 256) {
        const int r = c >> 3, q = c & 7;
        const bool v = (r < SEQ);
        const size_t go = base + (size_t)r * HDIM + q * 8;
        cp_async16(sb + QF_OFF + r * KSTR + q * 16, g_qf + (v ? go : base), v);
    }
    CP_COMMIT();

    for (int i = tid; i < 730; i += 256) sT[i] = __ldg(&table[i * H_NUM + h]);
    if (tid < 256) {
        int v = 0;
        if (tid >= 1) {
            const int pb = tid - 1;
            const int r = pb / 14;
            v = r * 27 + (pb - r * 14);
        }
        rcA[tid] = v;
    }
    CP_WAIT0();
    __syncthreads();

    const int wr = wid >> 1;
    const int wc = wid & 1;
    const uint32_t aRowSel = (lane & 7) + ((lane >> 3) & 1) * 8;
    const uint32_t aColSel = ((lane >> 4) & 1) * 16;
    const uint32_t bRow4 = (lane & 7) + ((lane >> 4) & 1) * 8;
    const uint32_t bCol4 = ((lane >> 3) & 1) * 16;
    const int rl0 = wr * 16 + (lane >> 2);
    const int rl1 = rl0 + 8;

    for (int nb = 0; nb < 4; nb++) {
        const int n0 = nb * 64;
        const uint32_t qb = sb + QF_OFF + (uint32_t)(nb & 1) * QBUF_B;

        float acc[13][4];
#pragma unroll
        for (int j = 0; j < 13; j++)
#pragma unroll
            for (int t = 0; t < 4; t++) acc[j][t] = 0.f;

#pragma unroll
        for (int ks = 0; ks < 4; ks++) {
            const uint32_t ra = qb + (wr * 16 + aRowSel) * KSTR + aColSel + ks * 32;
            uint32_t a_f[4];
            ldm_x4(a_f, ra);
#pragma unroll
            for (int p = 0; p < 6; p++) {
                uint32_t b4[4];
                const uint32_t rb = sb + KF_OFF +
                    (wc * 104 + p * 16 + bRow4) * KSTR + bCol4 + ks * 32;
                ldm_x4(b4, rb);
                mma_f16(acc[2 * p + 0], a_f, b4 + 0);
                mma_f16(acc[2 * p + 1], a_f, b4 + 2);
            }
            {
                uint32_t b_f[2];
                const uint32_t rb = sb + KF_OFF +
                    (wc * 104 + 96 + (lane & 7)) * KSTR + ((lane >> 3) & 1) * 16 + ks * 32;
                ldm_x2(b_f, rb);
                mma_f16(acc[12], a_f, b_f);
            }
        }

        if (nb < 3) {
            const uint32_t qn = sb + QF_OFF + (uint32_t)((nb + 1) & 1) * QBUF_B;
            for (int c = tid; c < 512; c += 256) {
                const int r = c >> 3, q = c & 7;
                const int n = n0 + 64 + r;
                const bool v = (n < SEQ);
                const size_t go = base + (size_t)n * HDIM + q * 8;
                cp_async16(qn + r * KSTR + q * 16, g_qf + (v ? go : base), v);
            }
        }
        CP_COMMIT();

        const int gn0 = n0 + rl0, gn1 = n0 + rl1;
        const int rcn0 = rcA[gn0 & 255], rcn1 = rcA[gn1 & 255];
        const bool v0r = (gn0 > 0 && gn0 < SEQ), v1r = (gn1 > 0 && gn1 < SEQ);
        float s0 = 0.f, s1 = 0.f;
#pragma unroll
        for (int j = 0; j < 13; j++) {
            const int c = wc * 104 + j * 8 + (lane & 3) * 2;
            float e00 = 0.f, e01 = 0.f, e10 = 0.f, e11 = 0.f;
#pragma unroll
            for (int e = 0; e < 2; e++) {
                const int m = c + e;
                if (m < SEQ) {
                    const int rcm = rcA[m];
                    const int bi0 = (!v0r || m == 0) ? 0 : rcm - rcn0 + 365;
                    const int bi1 = (!v1r || m == 0) ? 0 : rcm - rcn1 + 365;
                    const float x0 = __expf(acc[j][e]     * 0.125f + sT[bi0]);
                    const float x1 = __expf(acc[j][2 + e] * 0.125f + sT[bi1]);
                    if (e == 0) { e00 = x0; e10 = x1; }
                    else        { e01 = x0; e11 = x1; }
                }
            }
            s0 += e00 + e01;
            s1 += e10 + e11;
            *(__half2*)(smc + PF_OFF + rl0 * PSTR + c * 2) =
                __halves2half2(__float2half(e00), __float2half(e01));
            *(__half2*)(smc + PF_OFF + rl1 * PSTR + c * 2) =
                __halves2half2(__float2half(e10), __float2half(e11));
        }
        s0 += __shfl_xor_sync(0xffffffffu, s0, 1);
        s0 += __shfl_xor_sync(0xffffffffu, s0, 2);
        s1 += __shfl_xor_sync(0xffffffffu, s1, 1);
        s1 += __shfl_xor_sync(0xffffffffu, s1, 2);
        if ((lane & 3) == 0) {
            redS[rl0 * 2 + wc] = s0;
            redS[rl1 * 2 + wc] = s1;
        }
        __syncthreads();

        float o[4][4];
#pragma unroll
        for (int j = 0; j < 4; j++)
#pragma unroll
            for (int t = 0; t < 4; t++) o[j][t] = 0.f;

#pragma unroll
        for (int ks = 0; ks < 13; ks++) {
            const uint32_t ra = sb + PF_OFF + (wr * 16 + aRowSel) * PSTR + aColSel + ks * 32;
            uint32_t a_f[4];
            ldm_x4(a_f, ra);
#pragma unroll
            for (int p = 0; p < 2; p++) {
                uint32_t b4[4];
                const uint32_t rb = sb + VF_OFF +
                    (ks * 16 + (lane & 7) + ((lane >> 3) & 1) * 8) * KSTR +
                    (wc * 32 + p * 16 + ((lane >> 4) & 1) * 8) * 2;
                ldm_x4_t(b4, rb);
                mma_f16(o[2 * p + 0], a_f, b4 + 0);
                mma_f16(o[2 * p + 1], a_f, b4 + 2);
            }
        }

        const float inv0 = 1.0f / (redS[rl0 * 2] + redS[rl0 * 2 + 1]);
        const float inv1 = 1.0f / (redS[rl1 * 2] + redS[rl1 * 2 + 1]);
#pragma unroll
        for (int j = 0; j < 4; j++) {
            const int d = wc * 32 + j * 8 + (lane & 3) * 2;
#pragma unroll
            for (int half = 0; half < 2; half++) {
                const int gn = (half == 0) ? gn0 : gn1;
                if (gn >= SEQ) continue;
                const float inv = (half == 0) ? inv0 : inv1;
                const float w0 = o[j][half * 2 + 0] * inv;
                const float w1 = o[j][half * 2 + 1] * inv;
                const size_t off = ((size_t)(b * SEQ + gn)) * C_DIM + h * HDIM + d;
                *(__half2*)&g_aoh[off] = __halves2half2(__float2half(w0), __float2half(w1));
            }
        }

        CP_WAIT0();
        __syncthreads();
    }
}

// ---------------------------------------------------------------------------
extern "C" void kernel_launch(void* const* d_in, const int* in_sizes, int n_in,
                              void* d_out, int out_size)
{
    const float* x      = (const float*)d_in[0];
    const float* table  = (const float*)d_in[1];
    const float* w_qkv  = (const float*)d_in[2];
    const float* w_proj = (const float*)d_in[3];
    const float* b_proj = (const float*)d_in[4];
    float* out = (float*)d_out;

    cudaFuncSetAttribute(hmma_gemm<0>, cudaFuncAttributeMaxDynamicSharedMemorySize, GEMM_SMEM);
    cudaFuncSetAttribute(hmma_gemm<1>, cudaFuncAttributeMaxDynamicSharedMemorySize, GEMM_SMEM);
    cudaFuncSetAttribute(attn_hmma,   cudaFuncAttributeMaxDynamicSharedMemorySize, ATT_SMEM);

    // fp32 -> fp16 casts (single fused launch)
    cast_all<<<(N4ALL + 255) / 256, 256>>>(x, w_qkv, w_proj);

    // QKV projection (persistent, 296 CTAs) -> fp16 q/k/v
    hmma_gemm<0><<<G_CTAS, 256, GEMM_SMEM>>>(nullptr, nullptr);

    // fp16 attention with relative-position bias -> fp16 ao
    attn_hmma<<<B_SZ * H_NUM, 256, ATT_SMEM>>>(table);

    // Output projection (persistent, 296 CTAs)
    hmma_gemm<1><<<G_CTAS, 256, GEMM_SMEM>>>(b_proj, out);
}

// round 16
// speedup vs baseline: 1.0867x; 1.0867x over previous
#include <cuda_runtime.h>
#include <cuda_bf16.h>
#include <cuda_fp16.h>
#include <cstdint>

#define B_SZ   64
#define SEQ    197
#define C_DIM  768
#define H_NUM  12
#define HDIM   64
#define M_ROWS (B_SZ * SEQ)          // 12608

// ---------------------------------------------------------------------------
// Scratch (allocation-free: __device__ globals), all single fp16
// ---------------------------------------------------------------------------
__device__ __half g_xh [M_ROWS * C_DIM];            // x
__device__ __half g_wqh[3 * C_DIM * C_DIM];         // w_qkv
__device__ __half g_wph[C_DIM * C_DIM];             // w_proj
__device__ __half g_qf [B_SZ * H_NUM * SEQ * HDIM]; // q/k/v
__device__ __half g_kf [B_SZ * H_NUM * SEQ * HDIM];
__device__ __half g_vf [B_SZ * H_NUM * SEQ * HDIM];
__device__ __half g_aoh[M_ROWS * C_DIM];            // attn out

// ---------------------------------------------------------------------------
// Base-feature PTX helpers
// ---------------------------------------------------------------------------
__device__ __forceinline__ uint32_t smem_u32(const void* p) {
    uint32_t a;
    asm("{ .reg .u64 t; cvta.to.shared.u64 t, %1; cvt.u32.u64 %0, t; }"
        : "=r"(a) : "l"(p));
    return a;
}

__device__ __forceinline__ void cp_async16(uint32_t dst, const void* src, bool pred) {
    const int sz = pred ? 16 : 0;
    asm volatile("cp.async.cg.shared.global [%0], [%1], 16, %2;"
                 :: "r"(dst), "l"(src), "r"(sz) : "memory");
}
#define CP_COMMIT()  asm volatile("cp.async.commit_group;" ::: "memory")
#define CP_WAIT1()   asm volatile("cp.async.wait_group 1;" ::: "memory")
#define CP_WAIT0()   asm volatile("cp.async.wait_group 0;" ::: "memory")

__device__ __forceinline__ void ldm_x4(uint32_t* r, uint32_t addr) {
    asm volatile("ldmatrix.sync.aligned.m8n8.x4.shared.b16 {%0,%1,%2,%3}, [%4];"
                 : "=r"(r[0]), "=r"(r[1]), "=r"(r[2]), "=r"(r[3]) : "r"(addr));
}
__device__ __forceinline__ void ldm_x2(uint32_t* r, uint32_t addr) {
    asm volatile("ldmatrix.sync.aligned.m8n8.x2.shared.b16 {%0,%1}, [%2];"
                 : "=r"(r[0]), "=r"(r[1]) : "r"(addr));
}
__device__ __forceinline__ void ldm_x4_t(uint32_t* r, uint32_t addr) {
    asm volatile("ldmatrix.sync.aligned.m8n8.x4.trans.shared.b16 {%0,%1,%2,%3}, [%4];"
                 : "=r"(r[0]), "=r"(r[1]), "=r"(r[2]), "=r"(r[3]) : "r"(addr));
}
__device__ __forceinline__ void mma_f16(float* c, const uint32_t* a, const uint32_t* b) {
    asm volatile(
        "mma.sync.aligned.m16n8k16.row.col.f32.f16.f16.f32 "
        "{%0,%1,%2,%3}, {%4,%5,%6,%7}, {%8,%9}, {%0,%1,%2,%3};"
        : "+f"(c[0]), "+f"(c[1]), "+f"(c[2]), "+f"(c[3])
        : "r"(a[0]), "r"(a[1]), "r"(a[2]), "r"(a[3]), "r"(b[0]), "r"(b[1]));
}

// ---------------------------------------------------------------------------
// Fused fp32 -> fp16 cast: one launch; 8 floats per thread, 16B stores.
// ---------------------------------------------------------------------------
#define N8X (M_ROWS * C_DIM / 8)
#define N8Q (3 * C_DIM * C_DIM / 8)
#define N8P (C_DIM * C_DIM / 8)
#define N8ALL (N8X + N8Q + N8P)

__global__ __launch_bounds__(256)
void cast_all(const float* __restrict__ x, const float* __restrict__ wq,
              const float* __restrict__ wp)
{
    const int i = blockIdx.x * 256 + threadIdx.x;
    if (i >= N8ALL) return;
    const float* src;
    __half* dstb;
    int k;
    if (i < N8X)            { src = x;  dstb = g_xh;  k = i; }
    else if (i < N8X + N8Q) { src = wq; dstb = g_wqh; k = i - N8X; }
    else                    { src = wp; dstb = g_wph; k = i - N8X - N8Q; }
    const float4 v0 = ((const float4*)src)[k * 2 + 0];
    const float4 v1 = ((const float4*)src)[k * 2 + 1];
    __half2 h[4];
    h[0] = __halves2half2(__float2half(v0.x), __float2half(v0.y));
    h[1] = __halves2half2(__float2half(v0.z), __float2half(v0.w));
    h[2] = __halves2half2(__float2half(v1.x), __float2half(v1.y));
    h[3] = __halves2half2(__float2half(v1.z), __float2half(v1.w));
    ((uint4*)dstb)[k] = *(const uint4*)h;
}

// ---------------------------------------------------------------------------
// HMMA fp16 GEMM: C = A * B^T, K=768, fp32 accumulation.
// 128x128 CTA tile, 256 threads (8 warps = 2m x 4n), BK=64, 3-stage pipeline,
// 2 CTAs/SM. B fragments loaded pairwise via ldm_x4.
// MODE 0: A = g_xh, B = g_wqh -> fp16 q/k/v
// MODE 1: A = g_aoh, B = g_wph -> out + bias
// ---------------------------------------------------------------------------
#define ROW_B   144
#define A_MAT   (128 * ROW_B)
#define B_MAT   (128 * ROW_B)
#define A_O     0
#define BH_O    A_MAT
#define STG_B   (A_MAT + B_MAT)           // 36864
#define GEMM_SMEM (3 * STG_B)             // 110592
#define NIT     (C_DIM / 64)              // 12

template <int MODE>
__global__ __launch_bounds__(256, 2)
void hmma_gemm(const float* __restrict__ bias, float* __restrict__ out)
{
    extern __shared__ char smem[];
    const uint32_t sb = smem_u32(smem);
    const int tid  = threadIdx.x;
    const int wid  = tid >> 5, lane = tid & 31;
    const int wm   = wid & 1;
    const int wn   = wid >> 1;
    const int row0 = blockIdx.y * 128;
    const int col0 = blockIdx.x * 128;

    const __half* A = (MODE == 0) ? g_xh : g_aoh;
    const __half* B = (MODE == 0) ? g_wqh : g_wph;

    auto load_stage = [&](int s, int buf) {
        const uint32_t base = sb + (uint32_t)buf * STG_B;
        const int k0 = s * 64;
#pragma unroll
        for (int j = 0; j < 8; j++) {
            const int c = tid + j * 256;
            if (c < 1024) {
                const int r = c >> 3, q = c & 7;
                const int gr = row0 + r;
                const bool av = (gr < M_ROWS);
                const size_t off = (size_t)gr * C_DIM + k0 + q * 8;
                cp_async16(base + A_O + r * ROW_B + q * 16, A + off, av);
            } else {
                const int u = c - 1024;
                const int r = u >> 3, q = u & 7;
                const size_t off = (size_t)(col0 + r) * C_DIM + k0 + q * 8;
                cp_async16(base + BH_O + r * ROW_B + q * 16, B + off, true);
            }
        }
    };

    float acc[4][4][4];
#pragma unroll
    for (int mi = 0; mi < 4; mi++)
#pragma unroll
        for (int ni = 0; ni < 4; ni++)
#pragma unroll
            for (int t = 0; t < 4; t++) acc[mi][ni][t] = 0.f;

    // A x4 mapping: rows on bit3, 16B col-half on bit4
    const uint32_t aRowSel = (lane & 7) + ((lane >> 3) & 1) * 8;
    const uint32_t aColSel = ((lane >> 4) & 1) * 16;
    // B pairwise x4 mapping: rows on bit4, 16B col-half on bit3
    const uint32_t bRow4 = (lane & 7) + ((lane >> 4) & 1) * 8;
    const uint32_t bCol4 = ((lane >> 3) & 1) * 16;

    load_stage(0, 0);
    CP_COMMIT();
    load_stage(1, 1);
    CP_COMMIT();

    for (int it = 0; it < NIT; it++) {
        CP_WAIT1();
        __syncthreads();

        const uint32_t base = sb + (uint32_t)(it % 3) * STG_B;
#pragma unroll
        for (int ks = 0; ks < 4; ks++) {
            const uint32_t kb = ks * 32;
            uint32_t a_f[4][4];
#pragma unroll
            for (int mi = 0; mi < 4; mi++) {
                const uint32_t ra = base + A_O + (wm * 64 + mi * 16 + aRowSel) * ROW_B + aColSel + kb;
                ldm_x4(a_f[mi], ra);
            }
#pragma unroll
            for (int p = 0; p < 2; p++) {
                uint32_t b4[4];
                const uint32_t rb = base + BH_O + (wn * 32 + p * 16 + bRow4) * ROW_B + bCol4 + kb;
                ldm_x4(b4, rb);
#pragma unroll
                for (int mi = 0; mi < 4; mi++) {
                    mma_f16(acc[mi][2 * p + 0], a_f[mi], b4 + 0);
                    mma_f16(acc[mi][2 * p + 1], a_f[mi], b4 + 2);
                }
            }
        }

        if (it + 2 < NIT) load_stage(it + 2, (it + 2) % 3);
        CP_COMMIT();
    }

    // ---- epilogue ----
#pragma unroll
    for (int mi = 0; mi < 4; mi++) {
        const int rbase = row0 + wm * 64 + mi * 16 + (lane >> 2);
#pragma unroll
        for (int half = 0; half < 2; half++) {
            const int row = rbase + half * 8;
            if (row >= M_ROWS) continue;
            int bb = 0, n = 0;
            if (MODE == 0) { bb = row / SEQ; n = row - bb * SEQ; }
#pragma unroll
            for (int ni = 0; ni < 4; ni++) {
                const int col = col0 + wn * 32 + ni * 8 + 2 * (lane & 3);
                const float v0 = acc[mi][ni][half * 2 + 0];
                const float v1 = acc[mi][ni][half * 2 + 1];
                if (MODE == 0) {
                    const int which = col / C_DIM;
                    const int rem   = col - which * C_DIM;
                    const int h     = rem >> 6;
                    const int d     = rem & 63;
                    __half* dst = (which == 0) ? g_qf : (which == 1 ? g_kf : g_vf);
                    const size_t off = (((size_t)(bb * H_NUM + h)) * SEQ + n) * HDIM + d;
                    *(__half2*)&dst[off] =
                        __halves2half2(__float2half(v0), __float2half(v1));
                } else {
                    *(float2*)&out[(size_t)row * C_DIM + col] =
                        make_float2(v0 + __ldg(&bias[col]), v1 + __ldg(&bias[col + 1]));
                }
            }
        }
    }
}

// ---------------------------------------------------------------------------
// fp16 HMMA attention: one CTA per (b,h), 8 warps.
// No max-subtraction (scores are small), fused bias+exp pass,
// Q double-buffered, K via pairwise ldm_x4, V via ldm_x4.trans.
// ---------------------------------------------------------------------------
#define NP     208
#define KSTR   144
#define PSTR   432
#define KF_OFF 0
#define VF_OFF 29952
#define QF_OFF 59904
#define QBUF_B 9216
#define PF_OFF 78336
#define TB_OFF 105984
#define RC_OFF 109056
#define RS_OFF 110080
#define ATT_SMEM 110592

__global__ __launch_bounds__(256, 2)
void attn_hmma(const float* __restrict__ table)
{
    extern __shared__ char smc[];
    const uint32_t sb = smem_u32(smc);
    float* sT   = (float*)(smc + TB_OFF);
    int*   rcA  = (int*)(smc + RC_OFF);
    float* redS = (float*)(smc + RS_OFF);

    const int tid = threadIdx.x, wid = tid >> 5, lane = tid & 31;
    const int bh = blockIdx.x;
    const int b  = bh / H_NUM;
    const int h  = bh - b * H_NUM;
    const size_t base = (size_t)bh * SEQ * HDIM;

    // stage K, V (zero-filled beyond SEQ) and Q block 0
    for (int c = tid; c < NP * 8; c += 256) {
        const int m = c >> 3, q = c & 7;
        const bool v = (m < SEQ);
        const size_t go = base + (size_t)m * HDIM + q * 8;
        const uint32_t so = m * KSTR + q * 16;
        cp_async16(sb + KF_OFF + so, g_kf + (v ? go : base), v);
        cp_async16(sb + VF_OFF + so, g_vf + (v ? go : base), v);
    }
    for (int c = tid; c < 512; c += 256) {
        const int r = c >> 3, q = c & 7;
        const bool v = (r < SEQ);
        const size_t go = base + (size_t)r * HDIM + q * 8;
        cp_async16(sb + QF_OFF + r * KSTR + q * 16, g_qf + (v ? go : base), v);
    }
    CP_COMMIT();

    for (int i = tid; i < 730; i += 256) sT[i] = __ldg(&table[i * H_NUM + h]);
    if (tid < 256) {
        int v = 0;
        if (tid >= 1) {
            const int pb = tid - 1;
            const int r = pb / 14;
            v = r * 27 + (pb - r * 14);
        }
        rcA[tid] = v;
    }
    CP_WAIT0();
    __syncthreads();

    const int wr = wid >> 1;
    const int wc = wid & 1;
    const uint32_t aRowSel = (lane & 7) + ((lane >> 3) & 1) * 8;
    const uint32_t aColSel = ((lane >> 4) & 1) * 16;
    const uint32_t bRow4 = (lane & 7) + ((lane >> 4) & 1) * 8;
    const uint32_t bCol4 = ((lane >> 3) & 1) * 16;
    const int rl0 = wr * 16 + (lane >> 2);
    const int rl1 = rl0 + 8;

    for (int nb = 0; nb < 4; nb++) {
        const int n0 = nb * 64;
        const uint32_t qb = sb + QF_OFF + (uint32_t)(nb & 1) * QBUF_B;

        // ---- S = Q K^T (fp16), warp tile 16 x 104 ----
        float acc[13][4];
#pragma unroll
        for (int j = 0; j < 13; j++)
#pragma unroll
            for (int t = 0; t < 4; t++) acc[j][t] = 0.f;

#pragma unroll
        for (int ks = 0; ks < 4; ks++) {
            const uint32_t ra = qb + (wr * 16 + aRowSel) * KSTR + aColSel + ks * 32;
            uint32_t a_f[4];
            ldm_x4(a_f, ra);
#pragma unroll
            for (int p = 0; p < 6; p++) {
                uint32_t b4[4];
                const uint32_t rb = sb + KF_OFF +
                    (wc * 104 + p * 16 + bRow4) * KSTR + bCol4 + ks * 32;
                ldm_x4(b4, rb);
                mma_f16(acc[2 * p + 0], a_f, b4 + 0);
                mma_f16(acc[2 * p + 1], a_f, b4 + 2);
            }
            {   // j = 12 (rows 96..103 of this half)
                uint32_t b_f[2];
                const uint32_t rb = sb + KF_OFF +
                    (wc * 104 + 96 + (lane & 7)) * KSTR + ((lane >> 3) & 1) * 16 + ks * 32;
                ldm_x2(b_f, rb);
                mma_f16(acc[12], a_f, b_f);
            }
        }

        // prefetch next Q block
        if (nb < 3) {
            const uint32_t qn = sb + QF_OFF + (uint32_t)((nb + 1) & 1) * QBUF_B;
            for (int c = tid; c < 512; c += 256) {
                const int r = c >> 3, q = c & 7;
                const int n = n0 + 64 + r;
                const bool v = (n < SEQ);
                const size_t go = base + (size_t)n * HDIM + q * 8;
                cp_async16(qn + r * KSTR + q * 16, g_qf + (v ? go : base), v);
            }
        }
        CP_COMMIT();

        // ---- fused bias + exp + row sum + P store ----
        const int gn0 = n0 + rl0, gn1 = n0 + rl1;
        const int rcn0 = rcA[gn0 & 255], rcn1 = rcA[gn1 & 255];
        const bool v0r = (gn0 > 0 && gn0 < SEQ), v1r = (gn1 > 0 && gn1 < SEQ);
        float s0 = 0.f, s1 = 0.f;
#pragma unroll
        for (int j = 0; j < 13; j++) {
            const int c = wc * 104 + j * 8 + (lane & 3) * 2;
            float e00 = 0.f, e01 = 0.f, e10 = 0.f, e11 = 0.f;
#pragma unroll
            for (int e = 0; e < 2; e++) {
                const int m = c + e;
                if (m < SEQ) {
                    const int rcm = rcA[m];
                    const int bi0 = (!v0r || m == 0) ? 0 : rcm - rcn0 + 365;
                    const int bi1 = (!v1r || m == 0) ? 0 : rcm - rcn1 + 365;
                    const float x0 = __expf(acc[j][e]     * 0.125f + sT[bi0]);
                    const float x1 = __expf(acc[j][2 + e] * 0.125f + sT[bi1]);
                    if (e == 0) { e00 = x0; e10 = x1; }
                    else        { e01 = x0; e11 = x1; }
                }
            }
            s0 += e00 + e01;
            s1 += e10 + e11;
            *(__half2*)(smc + PF_OFF + rl0 * PSTR + c * 2) =
                __halves2half2(__float2half(e00), __float2half(e01));
            *(__half2*)(smc + PF_OFF + rl1 * PSTR + c * 2) =
                __halves2half2(__float2half(e10), __float2half(e11));
        }
        s0 += __shfl_xor_sync(0xffffffffu, s0, 1);
        s0 += __shfl_xor_sync(0xffffffffu, s0, 2);
        s1 += __shfl_xor_sync(0xffffffffu, s1, 1);
        s1 += __shfl_xor_sync(0xffffffffu, s1, 2);
        if ((lane & 3) == 0) {
            redS[rl0 * 2 + wc] = s0;
            redS[rl1 * 2 + wc] = s1;
        }
        __syncthreads();

        // ---- O = P V (fp16), warp tile 16 x 32, V via ldm_x4.trans ----
        float o[4][4];
#pragma unroll
        for (int j = 0; j < 4; j++)
#pragma unroll
            for (int t = 0; t < 4; t++) o[j][t] = 0.f;

#pragma unroll
        for (int ks = 0; ks < 13; ks++) {
            const uint32_t ra = sb + PF_OFF + (wr * 16 + aRowSel) * PSTR + aColSel + ks * 32;
            uint32_t a_f[4];
            ldm_x4(a_f, ra);
#pragma unroll
            for (int p = 0; p < 2; p++) {
                uint32_t b4[4];
                const uint32_t rb = sb + VF_OFF +
                    (ks * 16 + (lane & 7) + ((lane >> 3) & 1) * 8) * KSTR +
                    (wc * 32 + p * 16 + ((lane >> 4) & 1) * 8) * 2;
                ldm_x4_t(b4, rb);
                mma_f16(o[2 * p + 0], a_f, b4 + 0);
                mma_f16(o[2 * p + 1], a_f, b4 + 2);
            }
        }

        // ---- normalize + store fp16 ao ----
        const float inv0 = 1.0f / (redS[rl0 * 2] + redS[rl0 * 2 + 1]);
        const float inv1 = 1.0f / (redS[rl1 * 2] + redS[rl1 * 2 + 1]);
#pragma unroll
        for (int j = 0; j < 4; j++) {
            const int d = wc * 32 + j * 8 + (lane & 3) * 2;
#pragma unroll
            for (int half = 0; half < 2; half++) {
                const int gn = (half == 0) ? gn0 : gn1;
                if (gn >= SEQ) continue;
                const float inv = (half == 0) ? inv0 : inv1;
                const float w0 = o[j][half * 2 + 0] * inv;
                const float w1 = o[j][half * 2 + 1] * inv;
                const size_t off = ((size_t)(b * SEQ + gn)) * C_DIM + h * HDIM + d;
                *(__half2*)&g_aoh[off] = __halves2half2(__float2half(w0), __float2half(w1));
            }
        }

        CP_WAIT0();        // next Q landed
        __syncthreads();   // P reads done before next exp pass overwrites
    }
}

// ---------------------------------------------------------------------------
extern "C" void kernel_launch(void* const* d_in, const int* in_sizes, int n_in,
                              void* d_out, int out_size)
{
    const float* x      = (const float*)d_in[0];
    const float* table  = (const float*)d_in[1];
    const float* w_qkv  = (const float*)d_in[2];
    const float* w_proj = (const float*)d_in[3];
    const float* b_proj = (const float*)d_in[4];
    float* out = (float*)d_out;

    cudaFuncSetAttribute(hmma_gemm<0>, cudaFuncAttributeMaxDynamicSharedMemorySize, GEMM_SMEM);
    cudaFuncSetAttribute(hmma_gemm<1>, cudaFuncAttributeMaxDynamicSharedMemorySize, GEMM_SMEM);
    cudaFuncSetAttribute(attn_hmma,   cudaFuncAttributeMaxDynamicSharedMemorySize, ATT_SMEM);

    // fp32 -> fp16 casts (single fused launch, 8 floats/thread)
    cast_all<<<(N8ALL + 255) / 256, 256>>>(x, w_qkv, w_proj);

    // QKV projection (fp16) -> fp16 q/k/v
    hmma_gemm<0><<<dim3(3 * C_DIM / 128, (M_ROWS + 127) / 128), 256, GEMM_SMEM>>>(nullptr, nullptr);

    // fp16 attention with relative-position bias -> fp16 ao
    attn_hmma<<<B_SZ * H_NUM, 256, ATT_SMEM>>>(table);

    // Output projection (fp16)
    hmma_gemm<1><<<dim3(C_DIM / 128, (M_ROWS + 127) / 128), 256, GEMM_SMEM>>>(b_proj, out);
}

// round 17
// speedup vs baseline: 1.1445x; 1.0532x over previous
#include <cuda_runtime.h>
#include <cuda_bf16.h>
#include <cuda_fp16.h>
#include <cstdint>

#define B_SZ   64
#define SEQ    197
#define C_DIM  768
#define H_NUM  12
#define HDIM   64
#define M_ROWS (B_SZ * SEQ)          // 12608

// ---------------------------------------------------------------------------
// Scratch (allocation-free: __device__ globals), all single fp16
// ---------------------------------------------------------------------------
__device__ __half g_xh [M_ROWS * C_DIM];            // x
__device__ __half g_wqh[3 * C_DIM * C_DIM];         // w_qkv
__device__ __half g_wph[C_DIM * C_DIM];             // w_proj
__device__ __half g_qf [B_SZ * H_NUM * SEQ * HDIM]; // q/k/v
__device__ __half g_kf [B_SZ * H_NUM * SEQ * HDIM];
__device__ __half g_vf [B_SZ * H_NUM * SEQ * HDIM];
__device__ __half g_aoh[M_ROWS * C_DIM];            // attn out

// dependency flags (reset by cast_all each launch sequence)
__device__ int g_cnt0[99];   // per GEMM0 row-tile: #col-tiles done (18 = full)
__device__ int g_cnt2[64];   // per batch: #heads done (12 = full)

// ---------------------------------------------------------------------------
// Base-feature PTX helpers
// ---------------------------------------------------------------------------
__device__ __forceinline__ uint32_t smem_u32(const void* p) {
    uint32_t a;
    asm("{ .reg .u64 t; cvta.to.shared.u64 t, %1; cvt.u32.u64 %0, t; }"
        : "=r"(a) : "l"(p));
    return a;
}

__device__ __forceinline__ void cp_async16(uint32_t dst, const void* src, bool pred) {
    const int sz = pred ? 16 : 0;
    asm volatile("cp.async.cg.shared.global [%0], [%1], 16, %2;"
                 :: "r"(dst), "l"(src), "r"(sz) : "memory");
}
#define CP_COMMIT()  asm volatile("cp.async.commit_group;" ::: "memory")
#define CP_WAIT1()   asm volatile("cp.async.wait_group 1;" ::: "memory")
#define CP_WAIT0()   asm volatile("cp.async.wait_group 0;" ::: "memory")

__device__ __forceinline__ void ldm_x4(uint32_t* r, uint32_t addr) {
    asm volatile("ldmatrix.sync.aligned.m8n8.x4.shared.b16 {%0,%1,%2,%3}, [%4];"
                 : "=r"(r[0]), "=r"(r[1]), "=r"(r[2]), "=r"(r[3]) : "r"(addr));
}
__device__ __forceinline__ void ldm_x2(uint32_t* r, uint32_t addr) {
    asm volatile("ldmatrix.sync.aligned.m8n8.x2.shared.b16 {%0,%1}, [%2];"
                 : "=r"(r[0]), "=r"(r[1]) : "r"(addr));
}
__device__ __forceinline__ void ldm_x4_t(uint32_t* r, uint32_t addr) {
    asm volatile("ldmatrix.sync.aligned.m8n8.x4.trans.shared.b16 {%0,%1,%2,%3}, [%4];"
                 : "=r"(r[0]), "=r"(r[1]), "=r"(r[2]), "=r"(r[3]) : "r"(addr));
}
__device__ __forceinline__ void mma_f16(float* c, const uint32_t* a, const uint32_t* b) {
    asm volatile(
        "mma.sync.aligned.m16n8k16.row.col.f32.f16.f16.f32 "
        "{%0,%1,%2,%3}, {%4,%5,%6,%7}, {%8,%9}, {%0,%1,%2,%3};"
        : "+f"(c[0]), "+f"(c[1]), "+f"(c[2]), "+f"(c[3])
        : "r"(a[0]), "r"(a[1]), "r"(a[2]), "r"(a[3]), "r"(b[0]), "r"(b[1]));
}

// ---------------------------------------------------------------------------
// Fused fp32 -> fp16 cast + flag reset. 8 floats per thread, 16B stores.
// ---------------------------------------------------------------------------
#define N8X (M_ROWS * C_DIM / 8)
#define N8Q (3 * C_DIM * C_DIM / 8)
#define N8P (C_DIM * C_DIM / 8)
#define N8ALL (N8X + N8Q + N8P)

__global__ __launch_bounds__(256)
void cast_all(const float* __restrict__ x, const float* __restrict__ wq,
              const float* __restrict__ wp)
{
    const int i = blockIdx.x * 256 + threadIdx.x;
    if (i < 99) g_cnt0[i] = 0;
    else if (i < 163) g_cnt2[i - 99] = 0;
    if (i >= N8ALL) return;
    const float* src;
    __half* dstb;
    int k;
    if (i < N8X)            { src = x;  dstb = g_xh;  k = i; }
    else if (i < N8X + N8Q) { src = wq; dstb = g_wqh; k = i - N8X; }
    else                    { src = wp; dstb = g_wph; k = i - N8X - N8Q; }
    const float4 v0 = ((const float4*)src)[k * 2 + 0];
    const float4 v1 = ((const float4*)src)[k * 2 + 1];
    __half2 h[4];
    h[0] = __halves2half2(__float2half(v0.x), __float2half(v0.y));
    h[1] = __halves2half2(__float2half(v0.z), __float2half(v0.w));
    h[2] = __halves2half2(__float2half(v1.x), __float2half(v1.y));
    h[3] = __halves2half2(__float2half(v1.z), __float2half(v1.w));
    ((uint4*)dstb)[k] = *(const uint4*)h;
}

// ---------------------------------------------------------------------------
// GEMM section body: 128x128 tile, BK=64, 3-stage ring (identical to R16).
// MODE 0: x * w_qkv^T -> q/k/v, signals g_cnt0[rt].
// MODE 1: ao * w_proj^T + bias -> out, waits on g_cnt2.
// ---------------------------------------------------------------------------
#define ROW_B   144
#define A_MAT   (128 * ROW_B)
#define B_MAT   (128 * ROW_B)
#define A_O     0
#define BH_O    A_MAT
#define STG_B   (A_MAT + B_MAT)           // 36864
#define MEGA_SMEM (3 * STG_B)             // 110592
#define NIT     (C_DIM / 64)              // 12

template <int MODE>
__device__ __forceinline__ void gemm_body(int t, const float* __restrict__ bias,
                                          float* __restrict__ out)
{
    constexpr int NCT = (MODE == 0) ? 18 : 6;
    extern __shared__ char smem[];
    const uint32_t sb = smem_u32(smem);
    const int tid  = threadIdx.x;
    const int wid  = tid >> 5, lane = tid & 31;
    const int wm   = wid & 1;
    const int wn   = wid >> 1;
    const int rt   = t / NCT, ct = t - rt * NCT;
    const int row0 = rt * 128;
    const int col0 = ct * 128;

    const __half* A = (MODE == 0) ? g_xh : g_aoh;
    const __half* B = (MODE == 0) ? g_wqh : g_wph;

    if (MODE == 1) {
        // wait for all 12 heads of batches covered by this row-tile
        if (tid == 0) {
            const int b0 = row0 / SEQ;
            int b1 = (row0 + 127) / SEQ;
            if (b1 > B_SZ - 1) b1 = B_SZ - 1;
            for (int bb = b0; bb <= b1; bb++)
                while (((volatile int*)g_cnt2)[bb] < H_NUM) __nanosleep(128);
            __threadfence();
        }
        __syncthreads();
    }

    auto load_stage = [&](int s, int buf) {
        const uint32_t base = sb + (uint32_t)buf * STG_B;
        const int k0 = s * 64;
#pragma unroll
        for (int j = 0; j < 8; j++) {
            const int c = tid + j * 256;
            if (c < 1024) {
                const int r = c >> 3, q = c & 7;
                const int gr = row0 + r;
                const bool av = (gr < M_ROWS);
                const size_t off = (size_t)gr * C_DIM + k0 + q * 8;
                cp_async16(base + A_O + r * ROW_B + q * 16, A + off, av);
            } else {
                const int u = c - 1024;
                const int r = u >> 3, q = u & 7;
                const size_t off = (size_t)(col0 + r) * C_DIM + k0 + q * 8;
                cp_async16(base + BH_O + r * ROW_B + q * 16, B + off, true);
            }
        }
    };

    float acc[4][4][4];
#pragma unroll
    for (int mi = 0; mi < 4; mi++)
#pragma unroll
        for (int ni = 0; ni < 4; ni++)
#pragma unroll
            for (int tt = 0; tt < 4; tt++) acc[mi][ni][tt] = 0.f;

    const uint32_t aRowSel = (lane & 7) + ((lane >> 3) & 1) * 8;
    const uint32_t aColSel = ((lane >> 4) & 1) * 16;
    const uint32_t bRow4 = (lane & 7) + ((lane >> 4) & 1) * 8;
    const uint32_t bCol4 = ((lane >> 3) & 1) * 16;

    load_stage(0, 0);
    CP_COMMIT();
    load_stage(1, 1);
    CP_COMMIT();

    for (int it = 0; it < NIT; it++) {
        CP_WAIT1();
        __syncthreads();

        const uint32_t base = sb + (uint32_t)(it % 3) * STG_B;
#pragma unroll
        for (int ks = 0; ks < 4; ks++) {
            const uint32_t kb = ks * 32;
            uint32_t a_f[4][4];
#pragma unroll
            for (int mi = 0; mi < 4; mi++) {
                const uint32_t ra = base + A_O + (wm * 64 + mi * 16 + aRowSel) * ROW_B + aColSel + kb;
                ldm_x4(a_f[mi], ra);
            }
#pragma unroll
            for (int p = 0; p < 2; p++) {
                uint32_t b4[4];
                const uint32_t rb = base + BH_O + (wn * 32 + p * 16 + bRow4) * ROW_B + bCol4 + kb;
                ldm_x4(b4, rb);
#pragma unroll
                for (int mi = 0; mi < 4; mi++) {
                    mma_f16(acc[mi][2 * p + 0], a_f[mi], b4 + 0);
                    mma_f16(acc[mi][2 * p + 1], a_f[mi], b4 + 2);
                }
            }
        }

        if (it + 2 < NIT) load_stage(it + 2, (it + 2) % 3);
        CP_COMMIT();
    }

    // ---- epilogue ----
#pragma unroll
    for (int mi = 0; mi < 4; mi++) {
        const int rbase = row0 + wm * 64 + mi * 16 + (lane >> 2);
#pragma unroll
        for (int half = 0; half < 2; half++) {
            const int row = rbase + half * 8;
            if (row >= M_ROWS) continue;
            int bb = 0, n = 0;
            if (MODE == 0) { bb = row / SEQ; n = row - bb * SEQ; }
#pragma unroll
            for (int ni = 0; ni < 4; ni++) {
                const int col = col0 + wn * 32 + ni * 8 + 2 * (lane & 3);
                const float v0 = acc[mi][ni][half * 2 + 0];
                const float v1 = acc[mi][ni][half * 2 + 1];
                if (MODE == 0) {
                    const int which = col / C_DIM;
                    const int rem   = col - which * C_DIM;
                    const int h     = rem >> 6;
                    const int d     = rem & 63;
                    __half* dst = (which == 0) ? g_qf : (which == 1 ? g_kf : g_vf);
                    const size_t off = (((size_t)(bb * H_NUM + h)) * SEQ + n) * HDIM + d;
                    *(__half2*)&dst[off] =
                        __halves2half2(__float2half(v0), __float2half(v1));
                } else {
                    *(float2*)&out[(size_t)row * C_DIM + col] =
                        make_float2(v0 + __ldg(&bias[col]), v1 + __ldg(&bias[col + 1]));
                }
            }
        }
    }

    if (MODE == 0) {
        __threadfence();
        __syncthreads();
        if (tid == 0) atomicAdd(&g_cnt0[rt], 1);
    }
}

// ---------------------------------------------------------------------------
// Attention section body (identical math to R16). Waits on g_cnt0 row-tiles
// for its batch; signals g_cnt2[b] when done.
// ---------------------------------------------------------------------------
#define NP     208
#define KSTR   144
#define PSTR   432
#define KF_OFF 0
#define VF_OFF 29952
#define QF_OFF 59904
#define QBUF_B 9216
#define PF_OFF 78336
#define TB_OFF 105984
#define RC_OFF 109056
#define RS_OFF 110080

__device__ __forceinline__ void attn_body(int a, const float* __restrict__ table)
{
    extern __shared__ char smc[];
    const uint32_t sb = smem_u32(smc);
    float* sT   = (float*)(smc + TB_OFF);
    int*   rcA  = (int*)(smc + RC_OFF);
    float* redS = (float*)(smc + RS_OFF);

    const int tid = threadIdx.x, wid = tid >> 5, lane = tid & 31;
    const int b  = a / H_NUM;
    const int h  = a - b * H_NUM;
    const size_t base = (size_t)(b * H_NUM + h) * SEQ * HDIM;

    // wait for q/k/v rows of this batch (GEMM0 row-tiles rt0..rt1, all 18 cols)
    if (tid == 0) {
        const int rt0 = (b * SEQ) >> 7;
        const int rt1 = (b * SEQ + SEQ - 1) >> 7;
        for (int r = rt0; r <= rt1; r++)
            while (((volatile int*)g_cnt0)[r] < 18) __nanosleep(128);
        __threadfence();
    }
    __syncthreads();

    for (int c = tid; c < NP * 8; c += 256) {
        const int m = c >> 3, q = c & 7;
        const bool v = (m < SEQ);
        const size_t go = base + (size_t)m * HDIM + q * 8;
        const uint32_t so = m * KSTR + q * 16;
        cp_async16(sb + KF_OFF + so, g_kf + (v ? go : base), v);
        cp_async16(sb + VF_OFF + so, g_vf + (v ? go : base), v);
    }
    for (int c = tid; c < 512; c += 256) {
        const int r = c >> 3, q = c & 7;
        const bool v = (r < SEQ);
        const size_t go = base + (size_t)r * HDIM + q * 8;
        cp_async16(sb + QF_OFF + r * KSTR + q * 16, g_qf + (v ? go : base), v);
    }
    CP_COMMIT();

    for (int i = tid; i < 730; i += 256) sT[i] = __ldg(&table[i * H_NUM + h]);
    if (tid < 256) {
        int v = 0;
        if (tid >= 1) {
            const int pb = tid - 1;
            const int r = pb / 14;
            v = r * 27 + (pb - r * 14);
        }
        rcA[tid] = v;
    }
    CP_WAIT0();
    __syncthreads();

    const int wr = wid >> 1;
    const int wc = wid & 1;
    const uint32_t aRowSel = (lane & 7) + ((lane >> 3) & 1) * 8;
    const uint32_t aColSel = ((lane >> 4) & 1) * 16;
    const uint32_t bRow4 = (lane & 7) + ((lane >> 4) & 1) * 8;
    const uint32_t bCol4 = ((lane >> 3) & 1) * 16;
    const int rl0 = wr * 16 + (lane >> 2);
    const int rl1 = rl0 + 8;

    for (int nb = 0; nb < 4; nb++) {
        const int n0 = nb * 64;
        const uint32_t qb = sb + QF_OFF + (uint32_t)(nb & 1) * QBUF_B;

        float acc[13][4];
#pragma unroll
        for (int j = 0; j < 13; j++)
#pragma unroll
            for (int t = 0; t < 4; t++) acc[j][t] = 0.f;

#pragma unroll
        for (int ks = 0; ks < 4; ks++) {
            const uint32_t ra = qb + (wr * 16 + aRowSel) * KSTR + aColSel + ks * 32;
            uint32_t a_f[4];
            ldm_x4(a_f, ra);
#pragma unroll
            for (int p = 0; p < 6; p++) {
                uint32_t b4[4];
                const uint32_t rb = sb + KF_OFF +
                    (wc * 104 + p * 16 + bRow4) * KSTR + bCol4 + ks * 32;
                ldm_x4(b4, rb);
                mma_f16(acc[2 * p + 0], a_f, b4 + 0);
                mma_f16(acc[2 * p + 1], a_f, b4 + 2);
            }
            {
                uint32_t b_f[2];
                const uint32_t rb = sb + KF_OFF +
                    (wc * 104 + 96 + (lane & 7)) * KSTR + ((lane >> 3) & 1) * 16 + ks * 32;
                ldm_x2(b_f, rb);
                mma_f16(acc[12], a_f, b_f);
            }
        }

        if (nb < 3) {
            const uint32_t qn = sb + QF_OFF + (uint32_t)((nb + 1) & 1) * QBUF_B;
            for (int c = tid; c < 512; c += 256) {
                const int r = c >> 3, q = c & 7;
                const int n = n0 + 64 + r;
                const bool v = (n < SEQ);
                const size_t go = base + (size_t)n * HDIM + q * 8;
                cp_async16(qn + r * KSTR + q * 16, g_qf + (v ? go : base), v);
            }
        }
        CP_COMMIT();

        const int gn0 = n0 + rl0, gn1 = n0 + rl1;
        const int rcn0 = rcA[gn0 & 255], rcn1 = rcA[gn1 & 255];
        const bool v0r = (gn0 > 0 && gn0 < SEQ), v1r = (gn1 > 0 && gn1 < SEQ);
        float s0 = 0.f, s1 = 0.f;
#pragma unroll
        for (int j = 0; j < 13; j++) {
            const int c = wc * 104 + j * 8 + (lane & 3) * 2;
            float e00 = 0.f, e01 = 0.f, e10 = 0.f, e11 = 0.f;
#pragma unroll
            for (int e = 0; e < 2; e++) {
                const int m = c + e;
                if (m < SEQ) {
                    const int rcm = rcA[m];
                    const int bi0 = (!v0r || m == 0) ? 0 : rcm - rcn0 + 365;
                    const int bi1 = (!v1r || m == 0) ? 0 : rcm - rcn1 + 365;
                    const float x0 = __expf(acc[j][e]     * 0.125f + sT[bi0]);
                    const float x1 = __expf(acc[j][2 + e] * 0.125f + sT[bi1]);
                    if (e == 0) { e00 = x0; e10 = x1; }
                    else        { e01 = x0; e11 = x1; }
                }
            }
            s0 += e00 + e01;
            s1 += e10 + e11;
            *(__half2*)(smc + PF_OFF + rl0 * PSTR + c * 2) =
                __halves2half2(__float2half(e00), __float2half(e01));
            *(__half2*)(smc + PF_OFF + rl1 * PSTR + c * 2) =
                __halves2half2(__float2half(e10), __float2half(e11));
        }
        s0 += __shfl_xor_sync(0xffffffffu, s0, 1);
        s0 += __shfl_xor_sync(0xffffffffu, s0, 2);
        s1 += __shfl_xor_sync(0xffffffffu, s1, 1);
        s1 += __shfl_xor_sync(0xffffffffu, s1, 2);
        if ((lane & 3) == 0) {
            redS[rl0 * 2 + wc] = s0;
            redS[rl1 * 2 + wc] = s1;
        }
        __syncthreads();

        float o[4][4];
#pragma unroll
        for (int j = 0; j < 4; j++)
#pragma unroll
            for (int t = 0; t < 4; t++) o[j][t] = 0.f;

#pragma unroll
        for (int ks = 0; ks < 13; ks++) {
            const uint32_t ra = sb + PF_OFF + (wr * 16 + aRowSel) * PSTR + aColSel + ks * 32;
            uint32_t a_f[4];
            ldm_x4(a_f, ra);
#pragma unroll
            for (int p = 0; p < 2; p++) {
                uint32_t b4[4];
                const uint32_t rb = sb + VF_OFF +
                    (ks * 16 + (lane & 7) + ((lane >> 3) & 1) * 8) * KSTR +
                    (wc * 32 + p * 16 + ((lane >> 4) & 1) * 8) * 2;
                ldm_x4_t(b4, rb);
                mma_f16(o[2 * p + 0], a_f, b4 + 0);
                mma_f16(o[2 * p + 1], a_f, b4 + 2);
            }
        }

        const float inv0 = 1.0f / (redS[rl0 * 2] + redS[rl0 * 2 + 1]);
        const float inv1 = 1.0f / (redS[rl1 * 2] + redS[rl1 * 2 + 1]);
#pragma unroll
        for (int j = 0; j < 4; j++) {
            const int d = wc * 32 + j * 8 + (lane & 3) * 2;
#pragma unroll
            for (int half = 0; half < 2; half++) {
                const int gn = (half == 0) ? gn0 : gn1;
                if (gn >= SEQ) continue;
                const float inv = (half == 0) ? inv0 : inv1;
                const float w0 = o[j][half * 2 + 0] * inv;
                const float w1 = o[j][half * 2 + 1] * inv;
                const size_t off = ((size_t)(b * SEQ + gn)) * C_DIM + h * HDIM + d;
                *(__half2*)&g_aoh[off] = __halves2half2(__float2half(w0), __float2half(w1));
            }
        }

        CP_WAIT0();
        __syncthreads();
    }

    __threadfence();
    __syncthreads();
    if (tid == 0) atomicAdd(&g_cnt2[b], 1);
}

// ---------------------------------------------------------------------------
// Mega-kernel: sections dispatched by blockIdx, flag-ordered.
//   [0, 1782)      : GEMM0 tiles (signal cnt0)
//   [1782, 2550)   : attention (wait cnt0, signal cnt2)
//   [2550, 3144)   : GEMM1 tiles (wait cnt2)
// ---------------------------------------------------------------------------
#define N_G0   1782
#define N_ATT  768
#define N_G1   594
#define N_MEGA (N_G0 + N_ATT + N_G1)

__global__ __launch_bounds__(256, 2)
void mega(const float* __restrict__ table, const float* __restrict__ bias,
          float* __restrict__ out)
{
    const int bid = blockIdx.x;
    if (bid < N_G0)              gemm_body<0>(bid, nullptr, nullptr);
    else if (bid < N_G0 + N_ATT) attn_body(bid - N_G0, table);
    else                         gemm_body<1>(bid - N_G0 - N_ATT, bias, out);
}

// ---------------------------------------------------------------------------
extern "C" void kernel_launch(void* const* d_in, const int* in_sizes, int n_in,
                              void* d_out, int out_size)
{
    const float* x      = (const float*)d_in[0];
    const float* table  = (const float*)d_in[1];
    const float* w_qkv  = (const float*)d_in[2];
    const float* w_proj = (const float*)d_in[3];
    const float* b_proj = (const float*)d_in[4];
    float* out = (float*)d_out;

    cudaFuncSetAttribute(mega, cudaFuncAttributeMaxDynamicSharedMemorySize, MEGA_SMEM);

    // fp32 -> fp16 casts + flag reset (stream-ordered before mega)
    cast_all<<<(N8ALL + 255) / 256, 256>>>(x, w_qkv, w_proj);

    // fused GEMM0 -> attention -> GEMM1 with fine-grained flag dependencies
    mega<<<N_MEGA, 256, MEGA_SMEM>>>(table, b_proj, out);
}